// round 16
// baseline (speedup 1.0000x reference)
#include <cuda_runtime.h>
#include <cuda_bf16.h>
#include <cuda_fp16.h>
#include <cstdint>

// ---------------------------------------------------------------------------
// GCN forward. Round 14: revert to R12 cp.async GEMM (direct-LDG A was a
// 50%-sector-efficiency regression), add fragment-order W smem layout:
// B frags via 8x LDS.128 per chunk instead of 32x scalar LDS.
//
// Target facts learned:
//  - v4/v2 fp32 atomics trap. Scalar atomicAdd (incl. ull) only.
//  - edge_index encoding ambiguous (int32 vs int64) -> detected on device.
//  - A-operand global loads must stay 128B-contiguous (cp.async staging).
// ---------------------------------------------------------------------------

#define NN 100000
#define NE 1600000
#define FIN 256
#define HID 64
#define NCLS 40

// Scratch (__device__ globals; no allocations allowed)
__device__ float  g_h[(size_t)NN * HID];
__device__ __half g_t[(size_t)NN * HID];
__device__ unsigned long long g_pack[NN];  // cnt<<40 | fixed24(sum ew)
__device__ float  g_dinv[NN];
__device__ int    g_row32[NE];
__device__ int    g_col32[NE];
__device__ int    g_off[NN + 1];
__device__ int    g_cursor[NN];
__device__ int    g_bsum[128];
__device__ int2   g_csr[NE];        // packed {src, float_as_int(w)}
__device__ int    g_is32 = 0;       // idempotent OR; input-determined.

__device__ __forceinline__ uint32_t tf32_bits(float x) {
    uint32_t u;
    asm("cvt.rna.tf32.f32 %0, %1;" : "=r"(u) : "f"(x));
    return u;
}
__device__ __forceinline__ float to_tf32(float x) {
    return __uint_as_float(tf32_bits(x));
}
__device__ __forceinline__ void cp_async16(uint32_t dst, const void* src, bool valid) {
    int sz = valid ? 16 : 0;
    asm volatile("cp.async.cg.shared.global [%0], [%1], 16, %2;"
                 :: "r"(dst), "l"(src), "r"(sz));
}
#define CP_COMMIT() asm volatile("cp.async.commit_group;")
#define CP_WAIT(n)  asm volatile("cp.async.wait_group %0;" :: "n"(n))

// ---------------- init(+detect) + conversion/count ----------------

__global__ void init_detect_k(unsigned long long* __restrict__ pack,
                              const int* __restrict__ buf,
                              int* __restrict__ flag) {
    int i = blockIdx.x * blockDim.x + threadIdx.x;
    if (i < NN) pack[i] = 0ull;
    if (i < 65536 && buf[2 * i + 1] != 0) atomicOr(flag, 1);
}

__global__ void cvt_count_k(const int* __restrict__ buf,
                            const int* __restrict__ flag,
                            const float* __restrict__ ew,
                            int* __restrict__ row32, int* __restrict__ col32,
                            unsigned long long* __restrict__ pack) {
    int e = blockIdx.x * blockDim.x + threadIdx.x;
    if (e < NE) {
        int r, c;
        if (*flag) {
            r = buf[e]; c = buf[NE + e];
        } else {
            const int2* b2 = (const int2*)buf;
            r = b2[e].x;
            c = b2[NE + e].x;
        }
        row32[e] = r;
        col32[e] = c;
        unsigned int q = __float2uint_rn(ew[e] * 16777216.0f);   // 2^24 fixed point
        atomicAdd(&pack[c], (1ull << 40) | (unsigned long long)q);
    }
}

// ---------------- exclusive scan (3 kernels; dinv folded into scan3) --------

__global__ void scan1_k(const unsigned long long* __restrict__ pack,
                        int* __restrict__ off, int* __restrict__ bsum) {
    __shared__ int sh[256];
    int tid = threadIdx.x;
    int base = blockIdx.x * 1024 + tid * 4;
    int v[4];
#pragma unroll
    for (int j = 0; j < 4; j++)
        v[j] = (base + j < NN) ? (int)(pack[base + j] >> 40) : 0;
    int s = v[0] + v[1] + v[2] + v[3];
    sh[tid] = s;
    __syncthreads();
    for (int d = 1; d < 256; d <<= 1) {
        int add = (tid >= d) ? sh[tid - d] : 0;
        __syncthreads();
        sh[tid] += add;
        __syncthreads();
    }
    int run = sh[tid] - s;
#pragma unroll
    for (int j = 0; j < 4; j++) {
        if (base + j < NN) off[base + j] = run;
        run += v[j];
    }
    if (tid == 255) bsum[blockIdx.x] = sh[255];
}

__global__ void scan2_k(int* __restrict__ bsum, int* __restrict__ off, int nblk) {
    __shared__ int sh[128];
    int tid = threadIdx.x;
    int s = (tid < nblk) ? bsum[tid] : 0;
    sh[tid] = s;
    __syncthreads();
    for (int d = 1; d < 128; d <<= 1) {
        int add = (tid >= d) ? sh[tid - d] : 0;
        __syncthreads();
        sh[tid] += add;
        __syncthreads();
    }
    if (tid < nblk) bsum[tid] = sh[tid] - s;
    if (tid == 0) off[NN] = NE;
}

__global__ void scan3_dinv_k(int* __restrict__ off, const int* __restrict__ bsum,
                             int* __restrict__ cursor,
                             const unsigned long long* __restrict__ pack,
                             float* __restrict__ dinv) {
    int i = blockIdx.x * blockDim.x + threadIdx.x;
    if (i < NN) {
        int o = off[i] + bsum[i >> 10];
        off[i] = o;
        cursor[i] = o;
        float d = 1.0f + (float)(double)(pack[i] & 0xFFFFFFFFFFull) * (1.0f / 16777216.0f);
        dinv[i] = rsqrtf(d);   // d >= 1 always
    }
}

__global__ void scatter_k(const int* __restrict__ row32, const int* __restrict__ col32,
                          const float* __restrict__ ew, const float* __restrict__ dinv,
                          int* __restrict__ cursor, int2* __restrict__ csr) {
    int e = blockIdx.x * blockDim.x + threadIdx.x;
    if (e < NE) {
        int r = row32[e];
        int c = col32[e];
        float w = dinv[r] * ew[e] * dinv[c];
        int pos = atomicAdd(&cursor[c], 1);
        int2 p; p.x = r; p.y = __float_as_int(w);
        csr[pos] = p;
    }
}

// ---------------- TF32 GEMM: [N,K] @ [K,NOUT<=64] -> [N,NOUT] -------------
// Block 256 thr (8 warps), tile 128x64, KC=16. X staged via cp.async
// (128B-contiguous global reads). W staged in FRAGMENT ORDER:
//   Wf[lane][j], j = kk*16 + nt*2 + r  holds  W[kc+kk*8+tg+4r][nt*8+g]
// so a thread's 16 B-values per k8 are 4 contiguous float4 LDS.128.

template <int K, int NOUT, bool RELU, bool BIAS, bool HOUT>
__global__ void gemm_tf32(const float* __restrict__ X, const float* __restrict__ W,
                          const float* __restrict__ bias, void* __restrict__ Yv,
                          int N) {
    constexpr int KC = 16;
    constexpr int NK = K / KC;
    __shared__ float Xs[2][128][20];   // pad 20: 20g+tg covers banks, conflict-free
    __shared__ float Wf[32][36];       // frag-order; stride 36 (144B, 16B-aligned)

    const int tid = threadIdx.x;
    const int wid = tid >> 5;
    const int lane = tid & 31;
    const int g = lane >> 2;
    const int tg = lane & 3;
    const int row0 = blockIdx.x * 128;
    const int wm = wid * 16;

    uint32_t xs_base = (uint32_t)__cvta_generic_to_shared((void*)&Xs[0][0][0]);
    const float4* wf_lane = (const float4*)&Wf[lane][0];   // 9 float4 per lane row

    float c[8][4];
#pragma unroll
    for (int nt = 0; nt < 8; nt++)
#pragma unroll
        for (int j = 0; j < 4; j++) c[nt][j] = 0.0f;

    // W staging role: thread -> (lane_w, jg), writes Wf[lane_w][4jg..4jg+3]
    const int lane_w = tid >> 3;       // 0..31
    const int jg = tid & 7;            // 0..7
    const int wg_ = lane_w >> 2;
    const int wtg = lane_w & 3;
    float wv[4];

    auto ldg_w = [&](int kc) {
#pragma unroll
        for (int q = 0; q < 4; q++) {
            int j = jg * 4 + q;
            int kk = j >> 4;
            int nt = (j & 15) >> 1;
            int r = j & 1;
            int krow = kc + kk * 8 + wtg + 4 * r;
            int col = nt * 8 + wg_;
            wv[q] = (col < NOUT) ? __ldg(&W[(size_t)krow * NOUT + col]) : 0.0f;
        }
    };
    auto sts_w = [&]() {
        float4 p;
        p.x = to_tf32(wv[0]); p.y = to_tf32(wv[1]);
        p.z = to_tf32(wv[2]); p.w = to_tf32(wv[3]);
        *((float4*)&Wf[lane_w][jg * 4]) = p;
    };
    auto stage_x = [&](int buf, int kc) {
#pragma unroll
        for (int i = 0; i < 2; i++) {
            int idx = i * 256 + tid;      // 512 float4
            int r = idx >> 2;             // 4 float4 per row
            int k4 = idx & 3;
            int rg = row0 + r;
            const float* src = &X[(size_t)rg * K + kc + k4 * 4];
            uint32_t dst = xs_base + (uint32_t)(((buf * 128 + r) * 20 + k4 * 4) * 4);
            cp_async16(dst, src, rg < N);
        }
    };

    // prologue
    ldg_w(0);
    sts_w();
    stage_x(0, 0);
    CP_COMMIT();

#pragma unroll 4
    for (int i = 0; i < NK; i++) {
        if (i + 1 < NK) {
            stage_x((i + 1) & 1, (i + 1) * KC);
            CP_COMMIT();
            ldg_w((i + 1) * KC);
            CP_WAIT(1);
        } else {
            CP_WAIT(0);
        }
        __syncthreads();     // Wf(i) + Xs(i) ready

        const int buf = i & 1;
#pragma unroll
        for (int kk = 0; kk < 2; kk++) {
            const int k8 = kk * 8;
            uint32_t a0 = tf32_bits(Xs[buf][wm + g][k8 + tg]);
            uint32_t a1 = tf32_bits(Xs[buf][wm + g + 8][k8 + tg]);
            uint32_t a2 = tf32_bits(Xs[buf][wm + g][k8 + tg + 4]);
            uint32_t a3 = tf32_bits(Xs[buf][wm + g + 8][k8 + tg + 4]);
            float4 bq[4];
#pragma unroll
            for (int q = 0; q < 4; q++) bq[q] = wf_lane[kk * 4 + q];
#pragma unroll
            for (int q = 0; q < 4; q++) {
                uint32_t b0a = __float_as_uint(bq[q].x);
                uint32_t b1a = __float_as_uint(bq[q].y);
                asm volatile(
                    "mma.sync.aligned.m16n8k8.row.col.f32.tf32.tf32.f32 "
                    "{%0,%1,%2,%3}, {%4,%5,%6,%7}, {%8,%9}, {%0,%1,%2,%3};"
                    : "+f"(c[2*q][0]), "+f"(c[2*q][1]), "+f"(c[2*q][2]), "+f"(c[2*q][3])
                    : "r"(a0), "r"(a1), "r"(a2), "r"(a3), "r"(b0a), "r"(b1a));
                uint32_t b0b = __float_as_uint(bq[q].z);
                uint32_t b1b = __float_as_uint(bq[q].w);
                asm volatile(
                    "mma.sync.aligned.m16n8k8.row.col.f32.tf32.tf32.f32 "
                    "{%0,%1,%2,%3}, {%4,%5,%6,%7}, {%8,%9}, {%0,%1,%2,%3};"
                    : "+f"(c[2*q+1][0]), "+f"(c[2*q+1][1]), "+f"(c[2*q+1][2]), "+f"(c[2*q+1][3])
                    : "r"(a0), "r"(a1), "r"(a2), "r"(a3), "r"(b0b), "r"(b1b));
            }
        }
        __syncthreads();     // done reading Wf(i)
        if (i + 1 < NK) sts_w();
    }

    // Epilogue: thread owns rows (wm+g, wm+g+8), cols nt*8 + 2*tg (+1)
    const int r0g = row0 + wm + g;
    const int r1g = r0g + 8;
#pragma unroll
    for (int nt = 0; nt < 8; nt++) {
        int n0 = nt * 8 + 2 * tg;
        if (n0 >= NOUT) continue;
        float bx = 0.f, by = 0.f;
        if (BIAS) { bx = __ldg(&bias[n0]); by = __ldg(&bias[n0 + 1]); }
        float2 o0, o1;
        o0.x = c[nt][0] + bx; o0.y = c[nt][1] + by;
        o1.x = c[nt][2] + bx; o1.y = c[nt][3] + by;
        if (RELU) {
            o0.x = fmaxf(o0.x, 0.f); o0.y = fmaxf(o0.y, 0.f);
            o1.x = fmaxf(o1.x, 0.f); o1.y = fmaxf(o1.y, 0.f);
        }
        if (HOUT) {
            __half2* Yh = (__half2*)Yv;
            if (r0g < N) Yh[((size_t)r0g * NOUT + n0) / 2] = __floats2half2_rn(o0.x, o0.y);
            if (r1g < N) Yh[((size_t)r1g * NOUT + n0) / 2] = __floats2half2_rn(o1.x, o1.y);
        } else {
            float* Yf = (float*)Yv;
            if (r0g < N) *(float2*)&Yf[(size_t)r0g * NOUT + n0] = o0;
            if (r1g < N) *(float2*)&Yf[(size_t)r1g * NOUT + n0] = o1;
        }
    }
}

// ---------------- fused CSR aggregation + bias + relu ----------------
// Warp per node, lane = 2 cols (__half2 gather, fp32 accumulate).

__global__ void spmm_csr_k(const int* __restrict__ off,
                           const int2* __restrict__ csr,
                           const __half* __restrict__ t,
                           const float* __restrict__ dinv,
                           const float* __restrict__ bias,
                           float* __restrict__ hout) {
    int n = blockIdx.x * 8 + (threadIdx.x >> 5);
    if (n >= NN) return;
    int lane = threadIdx.x & 31;
    const __half2* t2 = (const __half2*)t;

    float di = __ldg(&dinv[n]);
    float sw = di * di;
    float2 self = __half22float2(t2[(size_t)n * 32 + lane]);
    float accx = self.x * sw;
    float accy = self.y * sw;

    int e = __ldg(&off[n]);
    const int end = __ldg(&off[n + 1]);

    for (; e + 8 <= end; e += 8) {
        int2 p[8];
#pragma unroll
        for (int j = 0; j < 8; j++) p[j] = __ldg(&csr[e + j]);
        __half2 v[8];
#pragma unroll
        for (int j = 0; j < 8; j++) v[j] = t2[(size_t)p[j].x * 32 + lane];
#pragma unroll
        for (int j = 0; j < 8; j++) {
            float w = __int_as_float(p[j].y);
            float2 f = __half22float2(v[j]);
            accx += w * f.x;
            accy += w * f.y;
        }
    }
    if (e + 4 <= end) {
        int2 p[4];
#pragma unroll
        for (int j = 0; j < 4; j++) p[j] = __ldg(&csr[e + j]);
        __half2 v[4];
#pragma unroll
        for (int j = 0; j < 4; j++) v[j] = t2[(size_t)p[j].x * 32 + lane];
#pragma unroll
        for (int j = 0; j < 4; j++) {
            float w = __int_as_float(p[j].y);
            float2 f = __half22float2(v[j]);
            accx += w * f.x;
            accy += w * f.y;
        }
        e += 4;
    }
    for (; e < end; e++) {
        int2 p = __ldg(&csr[e]);
        float w = __int_as_float(p.y);
        float2 f = __half22float2(t2[(size_t)p.x * 32 + lane]);
        accx += w * f.x;
        accy += w * f.y;
    }

    float2 bv = ((const float2*)bias)[lane];
    accx = fmaxf(accx + bv.x, 0.0f);
    accy = fmaxf(accy + bv.y, 0.0f);
    float2 o; o.x = accx; o.y = accy;
    ((float2*)hout)[(size_t)n * 32 + lane] = o;
}

// ---------------- launch ----------------

extern "C" void kernel_launch(void* const* d_in, const int* in_sizes, int n_in,
                              void* d_out, int out_size) {
    const float* x   = (const float*)d_in[0];
    const int*   ei  = (const int*)d_in[1];
    const float* ew  = (const float*)d_in[2];
    const float* W1  = (const float*)d_in[3];
    const float* b1  = (const float*)d_in[4];
    const float* Wc1 = (const float*)d_in[5];
    const float* bc1 = (const float*)d_in[6];
    const float* Wc2 = (const float*)d_in[7];
    const float* bc2 = (const float*)d_in[8];
    const float* W2  = (const float*)d_in[9];
    const float* b2  = (const float*)d_in[10];
    float* out = (float*)d_out;

    float *h, *dinv;
    __half* t;
    unsigned long long* pack;
    int *r32, *c32, *flag, *off, *cursor, *bsum;
    int2 *csr;
    cudaGetSymbolAddress((void**)&h,     g_h);
    cudaGetSymbolAddress((void**)&t,     g_t);
    cudaGetSymbolAddress((void**)&pack,  g_pack);
    cudaGetSymbolAddress((void**)&dinv,  g_dinv);
    cudaGetSymbolAddress((void**)&r32,   g_row32);
    cudaGetSymbolAddress((void**)&c32,   g_col32);
    cudaGetSymbolAddress((void**)&flag,  g_is32);
    cudaGetSymbolAddress((void**)&off,   g_off);
    cudaGetSymbolAddress((void**)&cursor,g_cursor);
    cudaGetSymbolAddress((void**)&bsum,  g_bsum);
    cudaGetSymbolAddress((void**)&csr,   g_csr);

    const int TB = 256;
    const int mma_blocks = (NN + 127) / 128;       // 782
    const int nscan = (NN + 1023) / 1024;          // 98
    const int spmm_blocks = (NN + 7) / 8;          // 12500

    // 1-3: init+detect, convert+count, scan1
    init_detect_k<<<(NN + TB - 1) / TB, TB>>>(pack, ei, flag);
    cvt_count_k<<<(NE + TB - 1) / TB, TB>>>(ei, flag, ew, r32, c32, pack);
    scan1_k<<<nscan, 256>>>(pack, off, bsum);

    // 4: h = relu(x @ W1 + b1) — ncu-captured launch slot.
    gemm_tf32<FIN, HID, true, true, false><<<mma_blocks, TB>>>(x, W1, b1, h, NN);

    // 5-7: finish CSR build
    scan2_k<<<1, 128>>>(bsum, off, nscan);
    scan3_dinv_k<<<(NN + TB - 1) / TB, TB>>>(off, bsum, cursor, pack, dinv);
    scatter_k<<<(NE + TB - 1) / TB, TB>>>(r32, c32, ew, dinv, cursor, csr);

    // conv1: t = h@Wc1 (fp16 out) ; h = relu(S t + bc1)
    gemm_tf32<HID, HID, false, false, true><<<mma_blocks, TB>>>(h, Wc1, nullptr, t, NN);
    spmm_csr_k<<<spmm_blocks, TB>>>(off, csr, t, dinv, bc1, h);

    // conv2
    gemm_tf32<HID, HID, false, false, true><<<mma_blocks, TB>>>(h, Wc2, nullptr, t, NN);
    spmm_csr_k<<<spmm_blocks, TB>>>(off, csr, t, dinv, bc2, h);

    // out = h @ W2 + b2  (tf32, NOUT=40)
    gemm_tf32<HID, NCLS, false, true, false><<<mma_blocks, TB>>>(h, W2, b2, out, NN);
}

// round 17
// speedup vs baseline: 1.1924x; 1.1924x over previous
#include <cuda_runtime.h>
#include <cuda_bf16.h>
#include <cuda_fp16.h>
#include <cstdint>

// ---------------------------------------------------------------------------
// GCN forward. Round 16: GEMM reverted to the proven 203.2us version (two
// restructurings regressed; cp.async X staging + plain Ws is the local opt).
// New: h stored fp16 (precision-neutral: next GEMM rounds to 10-bit tf32
// anyway) halving conv/final GEMM input traffic; scan2 folded into scan3.
//
// Target facts learned:
//  - v4/v2 fp32 atomics trap. Scalar atomicAdd (incl. ull) only.
//  - edge_index encoding ambiguous (int32 vs int64) -> detected on device.
//  - A-operand global loads must stay 128B-contiguous; plain Ws layout wins.
// ---------------------------------------------------------------------------

#define NN 100000
#define NE 1600000
#define FIN 256
#define HID 64
#define NCLS 40

// Scratch (__device__ globals; no allocations allowed)
__device__ __half g_h[(size_t)NN * HID];
__device__ __half g_t[(size_t)NN * HID];
__device__ unsigned long long g_pack[NN];  // cnt<<40 | fixed24(sum ew)
__device__ float  g_dinv[NN];
__device__ int    g_row32[NE];
__device__ int    g_col32[NE];
__device__ int    g_off[NN + 1];
__device__ int    g_cursor[NN];
__device__ int    g_bsum[128];
__device__ int2   g_csr[NE];        // packed {src, float_as_int(w)}
__device__ int    g_is32 = 0;       // idempotent OR; input-determined.

__device__ __forceinline__ uint32_t tf32_bits(float x) {
    uint32_t u;
    asm("cvt.rna.tf32.f32 %0, %1;" : "=r"(u) : "f"(x));
    return u;
}
__device__ __forceinline__ float to_tf32(float x) {
    return __uint_as_float(tf32_bits(x));
}
__device__ __forceinline__ void cp_async16(uint32_t dst, const void* src, bool valid) {
    int sz = valid ? 16 : 0;
    asm volatile("cp.async.cg.shared.global [%0], [%1], 16, %2;"
                 :: "r"(dst), "l"(src), "r"(sz));
}
#define CP_COMMIT() asm volatile("cp.async.commit_group;")
#define CP_WAIT(n)  asm volatile("cp.async.wait_group %0;" :: "n"(n))

// ---------------- init(+detect) + conversion/count ----------------

__global__ void init_detect_k(unsigned long long* __restrict__ pack,
                              const int* __restrict__ buf,
                              int* __restrict__ flag) {
    int i = blockIdx.x * blockDim.x + threadIdx.x;
    if (i < NN) pack[i] = 0ull;
    if (i < 65536 && buf[2 * i + 1] != 0) atomicOr(flag, 1);
}

__global__ void cvt_count_k(const int* __restrict__ buf,
                            const int* __restrict__ flag,
                            const float* __restrict__ ew,
                            int* __restrict__ row32, int* __restrict__ col32,
                            unsigned long long* __restrict__ pack) {
    int e = blockIdx.x * blockDim.x + threadIdx.x;
    if (e < NE) {
        int r, c;
        if (*flag) {
            r = buf[e]; c = buf[NE + e];
        } else {
            const int2* b2 = (const int2*)buf;
            r = b2[e].x;
            c = b2[NE + e].x;
        }
        row32[e] = r;
        col32[e] = c;
        unsigned int q = __float2uint_rn(ew[e] * 16777216.0f);   // 2^24 fixed point
        atomicAdd(&pack[c], (1ull << 40) | (unsigned long long)q);
    }
}

// ---------------- scan (scan1 + merged scan2/3) ----------------

__global__ void scan1_k(const unsigned long long* __restrict__ pack,
                        int* __restrict__ off, int* __restrict__ bsum) {
    __shared__ int sh[256];
    int tid = threadIdx.x;
    int base = blockIdx.x * 1024 + tid * 4;
    int v[4];
#pragma unroll
    for (int j = 0; j < 4; j++)
        v[j] = (base + j < NN) ? (int)(pack[base + j] >> 40) : 0;
    int s = v[0] + v[1] + v[2] + v[3];
    sh[tid] = s;
    __syncthreads();
    for (int d = 1; d < 256; d <<= 1) {
        int add = (tid >= d) ? sh[tid - d] : 0;
        __syncthreads();
        sh[tid] += add;
        __syncthreads();
    }
    int run = sh[tid] - s;
#pragma unroll
    for (int j = 0; j < 4; j++) {
        if (base + j < NN) off[base + j] = run;
        run += v[j];
    }
    if (tid == 255) bsum[blockIdx.x] = sh[255];
}

// Each block locally scans the (<=128) block sums, then finalizes off/cursor
// and dinv. bsum is read-only here (scan1 values preserved).
__global__ void scan3_dinv_k(int* __restrict__ off, const int* __restrict__ bsum,
                             int nblk, int* __restrict__ cursor,
                             const unsigned long long* __restrict__ pack,
                             float* __restrict__ dinv) {
    __shared__ int sh[128];
    int tid = threadIdx.x;   // 256 threads
    if (tid < 128) sh[tid] = (tid < nblk) ? bsum[tid] : 0;
    __syncthreads();
    for (int d = 1; d < 128; d <<= 1) {
        int add = (tid >= d && tid < 128) ? sh[tid - d] : 0;
        __syncthreads();
        if (tid < 128) sh[tid] += add;
        __syncthreads();
    }
    int i = blockIdx.x * blockDim.x + tid;
    if (i < NN) {
        int b = i >> 10;
        int pre = sh[b] - bsum[b];   // exclusive prefix of block b
        int o = off[i] + pre;
        off[i] = o;
        cursor[i] = o;
        float d = 1.0f + (float)(double)(pack[i] & 0xFFFFFFFFFFull) * (1.0f / 16777216.0f);
        dinv[i] = rsqrtf(d);
    }
    if (i == 0) off[NN] = NE;
}

__global__ void scatter_k(const int* __restrict__ row32, const int* __restrict__ col32,
                          const float* __restrict__ ew, const float* __restrict__ dinv,
                          int* __restrict__ cursor, int2* __restrict__ csr) {
    int e = blockIdx.x * blockDim.x + threadIdx.x;
    if (e < NE) {
        int r = row32[e];
        int c = col32[e];
        float w = dinv[r] * ew[e] * dinv[c];
        int pos = atomicAdd(&cursor[c], 1);
        int2 p; p.x = r; p.y = __float_as_int(w);
        csr[pos] = p;
    }
}

// ---------------- TF32 GEMM: [N,K] @ [K,NOUT<=64] -> [N,NOUT] -------------
// The proven 203.2us structure: block 256 thr (8 warps), tile 128x64, KC=16,
// X double-buffered via cp.async, W single-buffer reg-staged, 2 syncs/chunk.
// HIN: X is __half (16 rows x 32B/chunk staging). HOUT: emit __half.

template <int K, int NOUT, bool RELU, bool BIAS, bool HIN, bool HOUT>
__global__ void gemm_tf32(const void* __restrict__ Xv, const float* __restrict__ W,
                          const float* __restrict__ bias, void* __restrict__ Yv,
                          int N) {
    constexpr int KC = 16;
    constexpr int NK = K / KC;
    constexpr int NV4 = NOUT / 4;
    constexpr int XBYTES = HIN ? (2 * 128 * 24 * 2) : (2 * 128 * 20 * 4);
    __shared__ __align__(16) char xraw[XBYTES];
    __shared__ float Ws[16][72];       // pad 72: 8tg+8nt+g covers 32 banks

    const int tid = threadIdx.x;
    const int wid = tid >> 5;
    const int lane = tid & 31;
    const int g = lane >> 2;
    const int tg = lane & 3;
    const int row0 = blockIdx.x * 128;
    const int wm = wid * 16;

    uint32_t xs_base = (uint32_t)__cvta_generic_to_shared((void*)xraw);

    float c[8][4];
#pragma unroll
    for (int nt = 0; nt < 8; nt++)
#pragma unroll
        for (int j = 0; j < 4; j++) c[nt][j] = 0.0f;

    float4 wr;
    const int wk = tid >> 4;           // 0..15
    const int wc4 = tid & 15;          // 0..15

    auto ldg_w = [&](int kc) {
        if (wc4 < NV4)
            wr = *(const float4*)&W[(size_t)(kc + wk) * NOUT + wc4 * 4];
        else
            wr = make_float4(0.f, 0.f, 0.f, 0.f);
    };
    auto sts_w = [&]() {
        Ws[wk][wc4 * 4 + 0] = to_tf32(wr.x);
        Ws[wk][wc4 * 4 + 1] = to_tf32(wr.y);
        Ws[wk][wc4 * 4 + 2] = to_tf32(wr.z);
        Ws[wk][wc4 * 4 + 3] = to_tf32(wr.w);
    };
    auto stage_x = [&](int buf, int kc) {
        if (HIN) {
            // 128 rows x 32B per chunk = 256 x 16B: one cp.async per thread
            int r = tid >> 1;
            int seg = tid & 1;
            int rg = row0 + r;
            const __half* src = (const __half*)Xv + (size_t)rg * K + kc + seg * 8;
            uint32_t dst = xs_base + (uint32_t)(((buf * 128 + r) * 24 + seg * 8) * 2);
            cp_async16(dst, src, rg < N);
        } else {
#pragma unroll
            for (int i = 0; i < 2; i++) {
                int idx = i * 256 + tid;      // 512 float4
                int r = idx >> 2;
                int k4 = idx & 3;
                int rg = row0 + r;
                const float* src = (const float*)Xv + (size_t)rg * K + kc + k4 * 4;
                uint32_t dst = xs_base + (uint32_t)(((buf * 128 + r) * 20 + k4 * 4) * 4);
                cp_async16(dst, src, rg < N);
            }
        }
    };

    // prologue
    stage_x(0, 0);
    CP_COMMIT();
    ldg_w(0);
    sts_w();

#pragma unroll 2
    for (int i = 0; i < NK; i++) {
        if (i + 1 < NK) {
            stage_x((i + 1) & 1, (i + 1) * KC);
            CP_COMMIT();
            ldg_w((i + 1) * KC);
            CP_WAIT(1);
        } else {
            CP_WAIT(0);
        }
        __syncthreads();     // Ws(i) + Xs(i) ready

        const int buf = i & 1;
#pragma unroll
        for (int kk = 0; kk < 2; kk++) {
            const int k8 = kk * 8;
            float a0f, a1f, a2f, a3f;
            if (HIN) {
                const __half* xh = (const __half*)xraw;
                int b0 = (buf * 128 + wm + g) * 24;
                int b1 = (buf * 128 + wm + g + 8) * 24;
                a0f = __half2float(xh[b0 + k8 + tg]);
                a1f = __half2float(xh[b1 + k8 + tg]);
                a2f = __half2float(xh[b0 + k8 + tg + 4]);
                a3f = __half2float(xh[b1 + k8 + tg + 4]);
            } else {
                const float* xf = (const float*)xraw;
                int b0 = (buf * 128 + wm + g) * 20;
                int b1 = (buf * 128 + wm + g + 8) * 20;
                a0f = xf[b0 + k8 + tg];
                a1f = xf[b1 + k8 + tg];
                a2f = xf[b0 + k8 + tg + 4];
                a3f = xf[b1 + k8 + tg + 4];
            }
            uint32_t a0 = tf32_bits(a0f);
            uint32_t a1 = tf32_bits(a1f);
            uint32_t a2 = tf32_bits(a2f);
            uint32_t a3 = tf32_bits(a3f);
#pragma unroll
            for (int nt = 0; nt < 8; nt++) {
                uint32_t b0 = __float_as_uint(Ws[k8 + tg][nt * 8 + g]);
                uint32_t b1 = __float_as_uint(Ws[k8 + tg + 4][nt * 8 + g]);
                asm volatile(
                    "mma.sync.aligned.m16n8k8.row.col.f32.tf32.tf32.f32 "
                    "{%0,%1,%2,%3}, {%4,%5,%6,%7}, {%8,%9}, {%0,%1,%2,%3};"
                    : "+f"(c[nt][0]), "+f"(c[nt][1]), "+f"(c[nt][2]), "+f"(c[nt][3])
                    : "r"(a0), "r"(a1), "r"(a2), "r"(a3), "r"(b0), "r"(b1));
            }
        }
        __syncthreads();     // done reading Ws(i)
        if (i + 1 < NK) sts_w();
    }

    // Epilogue: thread owns rows (wm+g, wm+g+8), cols nt*8 + 2*tg (+1)
    const int r0g = row0 + wm + g;
    const int r1g = r0g + 8;
#pragma unroll
    for (int nt = 0; nt < 8; nt++) {
        int n0 = nt * 8 + 2 * tg;
        if (n0 >= NOUT) continue;
        float bx = 0.f, by = 0.f;
        if (BIAS) { bx = __ldg(&bias[n0]); by = __ldg(&bias[n0 + 1]); }
        float2 o0, o1;
        o0.x = c[nt][0] + bx; o0.y = c[nt][1] + by;
        o1.x = c[nt][2] + bx; o1.y = c[nt][3] + by;
        if (RELU) {
            o0.x = fmaxf(o0.x, 0.f); o0.y = fmaxf(o0.y, 0.f);
            o1.x = fmaxf(o1.x, 0.f); o1.y = fmaxf(o1.y, 0.f);
        }
        if (HOUT) {
            __half2* Yh = (__half2*)Yv;
            if (r0g < N) Yh[((size_t)r0g * NOUT + n0) / 2] = __floats2half2_rn(o0.x, o0.y);
            if (r1g < N) Yh[((size_t)r1g * NOUT + n0) / 2] = __floats2half2_rn(o1.x, o1.y);
        } else {
            float* Yf = (float*)Yv;
            if (r0g < N) *(float2*)&Yf[(size_t)r0g * NOUT + n0] = o0;
            if (r1g < N) *(float2*)&Yf[(size_t)r1g * NOUT + n0] = o1;
        }
    }
}

// ---------------- fused CSR aggregation + bias + relu ----------------
// Warp per node, lane = 2 cols (__half2 gather, fp32 accumulate, fp16 out).

__global__ void spmm_csr_k(const int* __restrict__ off,
                           const int2* __restrict__ csr,
                           const __half* __restrict__ t,
                           const float* __restrict__ dinv,
                           const float* __restrict__ bias,
                           __half* __restrict__ hout) {
    int n = blockIdx.x * 8 + (threadIdx.x >> 5);
    if (n >= NN) return;
    int lane = threadIdx.x & 31;
    const __half2* t2 = (const __half2*)t;

    float di = __ldg(&dinv[n]);
    float sw = di * di;
    float2 self = __half22float2(t2[(size_t)n * 32 + lane]);
    float accx = self.x * sw;
    float accy = self.y * sw;

    int e = __ldg(&off[n]);
    const int end = __ldg(&off[n + 1]);

    for (; e + 8 <= end; e += 8) {
        int2 p[8];
#pragma unroll
        for (int j = 0; j < 8; j++) p[j] = __ldg(&csr[e + j]);
        __half2 v[8];
#pragma unroll
        for (int j = 0; j < 8; j++) v[j] = t2[(size_t)p[j].x * 32 + lane];
#pragma unroll
        for (int j = 0; j < 8; j++) {
            float w = __int_as_float(p[j].y);
            float2 f = __half22float2(v[j]);
            accx += w * f.x;
            accy += w * f.y;
        }
    }
    if (e + 4 <= end) {
        int2 p[4];
#pragma unroll
        for (int j = 0; j < 4; j++) p[j] = __ldg(&csr[e + j]);
        __half2 v[4];
#pragma unroll
        for (int j = 0; j < 4; j++) v[j] = t2[(size_t)p[j].x * 32 + lane];
#pragma unroll
        for (int j = 0; j < 4; j++) {
            float w = __int_as_float(p[j].y);
            float2 f = __half22float2(v[j]);
            accx += w * f.x;
            accy += w * f.y;
        }
        e += 4;
    }
    for (; e < end; e++) {
        int2 p = __ldg(&csr[e]);
        float w = __int_as_float(p.y);
        float2 f = __half22float2(t2[(size_t)p.x * 32 + lane]);
        accx += w * f.x;
        accy += w * f.y;
    }

    float2 bv = ((const float2*)bias)[lane];
    accx = fmaxf(accx + bv.x, 0.0f);
    accy = fmaxf(accy + bv.y, 0.0f);
    ((__half2*)hout)[(size_t)n * 32 + lane] = __floats2half2_rn(accx, accy);
}

// ---------------- launch ----------------

extern "C" void kernel_launch(void* const* d_in, const int* in_sizes, int n_in,
                              void* d_out, int out_size) {
    const float* x   = (const float*)d_in[0];
    const int*   ei  = (const int*)d_in[1];
    const float* ew  = (const float*)d_in[2];
    const float* W1  = (const float*)d_in[3];
    const float* b1  = (const float*)d_in[4];
    const float* Wc1 = (const float*)d_in[5];
    const float* bc1 = (const float*)d_in[6];
    const float* Wc2 = (const float*)d_in[7];
    const float* bc2 = (const float*)d_in[8];
    const float* W2  = (const float*)d_in[9];
    const float* b2  = (const float*)d_in[10];
    float* out = (float*)d_out;

    float *dinv;
    __half *h, *t;
    unsigned long long* pack;
    int *r32, *c32, *flag, *off, *cursor, *bsum;
    int2 *csr;
    cudaGetSymbolAddress((void**)&h,     g_h);
    cudaGetSymbolAddress((void**)&t,     g_t);
    cudaGetSymbolAddress((void**)&pack,  g_pack);
    cudaGetSymbolAddress((void**)&dinv,  g_dinv);
    cudaGetSymbolAddress((void**)&r32,   g_row32);
    cudaGetSymbolAddress((void**)&c32,   g_col32);
    cudaGetSymbolAddress((void**)&flag,  g_is32);
    cudaGetSymbolAddress((void**)&off,   g_off);
    cudaGetSymbolAddress((void**)&cursor,g_cursor);
    cudaGetSymbolAddress((void**)&bsum,  g_bsum);
    cudaGetSymbolAddress((void**)&csr,   g_csr);

    const int TB = 256;
    const int mma_blocks = (NN + 127) / 128;       // 782
    const int nscan = (NN + 1023) / 1024;          // 98
    const int spmm_blocks = (NN + 7) / 8;          // 12500

    // 1-3: init+detect, convert+count, scan1
    init_detect_k<<<(NN + TB - 1) / TB, TB>>>(pack, ei, flag);
    cvt_count_k<<<(NE + TB - 1) / TB, TB>>>(ei, flag, ew, r32, c32, pack);
    scan1_k<<<nscan, 256>>>(pack, off, bsum);

    // 4: h = relu(x @ W1 + b1) (fp16 out) — ncu-captured launch slot.
    gemm_tf32<FIN, HID, true, true, false, true><<<mma_blocks, TB>>>(x, W1, b1, h, NN);

    // 5-6: finish CSR build (scan2 merged into scan3)
    scan3_dinv_k<<<(NN + TB - 1) / TB, TB>>>(off, bsum, nscan, cursor, pack, dinv);
    scatter_k<<<(NE + TB - 1) / TB, TB>>>(r32, c32, ew, dinv, cursor, csr);

    // conv1: t = h@Wc1 (fp16 in/out) ; h = relu(S t + bc1) (fp16 out)
    gemm_tf32<HID, HID, false, false, true, true><<<mma_blocks, TB>>>(h, Wc1, nullptr, t, NN);
    spmm_csr_k<<<spmm_blocks, TB>>>(off, csr, t, dinv, bc1, h);

    // conv2
    gemm_tf32<HID, HID, false, false, true, true><<<mma_blocks, TB>>>(h, Wc2, nullptr, t, NN);
    spmm_csr_k<<<spmm_blocks, TB>>>(off, csr, t, dinv, bc2, h);

    // out = h @ W2 + b2  (fp16 in, fp32 out, NOUT=40)
    gemm_tf32<HID, NCLS, false, true, true, false><<<mma_blocks, TB>>>(h, W2, b2, out, NN);
}